// round 4
// baseline (speedup 1.0000x reference)
#include <cuda_runtime.h>

// SimilarityMeasureModel on GB300 (sm_103a) — R4: row-locality experiment.
// Inputs: x, y [B=32, P=3, C=512, N=1024] f32 (N contiguous).
// Per (b,p,n): l1 = sum_c |x-y|, l2 = sum_c (x-y)^2 ; out = [l1,l2,l1].
//
// Kernel 1: block = (bp, c-segment). 256 threads cover one full 4KB row
// (float4 each); block marches 64 consecutive c values -> each block streams
// a fully CONTIGUOUS 256KB span of x and y (DRAM page-hit friendly), writing
// per-segment partial sums to device scratch.
// Kernel 2: folds the 8 segment partials per pair and writes [l1,l2,l1].

static constexpr int B = 32;
static constexpr int P = 3;
static constexpr int C = 512;
static constexpr int N = 1024;
static constexpr int N4 = N / 4;           // 256 float4 per row
static constexpr int BP = B * P;           // 96
static constexpr int SEGS = 8;
static constexpr int CSEG = C / SEGS;      // 64
static constexpr int BLOCKS1 = BP * SEGS;  // 768
static constexpr int PAIRS = BP * N;       // 98304

// Partial sums: [seg][bp][n4] as float4
__device__ float4 g_pl1[SEGS * BP * N4];
__device__ float4 g_pl2[SEGS * BP * N4];

__global__ void __launch_bounds__(256, 4)
sim_partial_kernel(const float4* __restrict__ x,
                   const float4* __restrict__ y) {
    const int bid = blockIdx.x;
    const int bp  = bid >> 3;               // 0..95
    const int cs  = bid & 7;                // C-segment 0..7

    const int n4 = threadIdx.x;             // 0..255 : float4 column in row

    // element (bp, c, n4) at (bp*C + c)*N4 + n4 ; start c = cs*CSEG
    size_t idx = ((size_t)bp * C + (size_t)cs * CSEG) * N4 + n4;

    float4 l1 = make_float4(0.f, 0.f, 0.f, 0.f);
    float4 l2 = make_float4(0.f, 0.f, 0.f, 0.f);

    #pragma unroll 4
    for (int c = 0; c < CSEG; ++c) {
        float4 a = __ldg(x + idx);
        float4 b = __ldg(y + idx);
        idx += N4;
        float d0 = a.x - b.x, d1 = a.y - b.y, d2 = a.z - b.z, d3 = a.w - b.w;
        l1.x += fabsf(d0); l1.y += fabsf(d1); l1.z += fabsf(d2); l1.w += fabsf(d3);
        l2.x = fmaf(d0, d0, l2.x); l2.y = fmaf(d1, d1, l2.y);
        l2.z = fmaf(d2, d2, l2.z); l2.w = fmaf(d3, d3, l2.w);
    }

    const size_t po = ((size_t)cs * BP + bp) * N4 + n4;
    g_pl1[po] = l1;
    g_pl2[po] = l2;
}

__global__ void __launch_bounds__(256)
sim_combine_kernel(float* __restrict__ out) {
    const int pair = blockIdx.x * 256 + threadIdx.x;   // 0..PAIRS-1
    const int bp = pair >> 10;        // /N
    const int n  = pair & (N - 1);
    const int n4 = n >> 2;
    const int j  = n & 3;

    const float* pl1 = (const float*)g_pl1;
    const float* pl2 = (const float*)g_pl2;

    float a1 = 0.f, a2 = 0.f;
    #pragma unroll
    for (int cs = 0; cs < SEGS; ++cs) {
        const size_t f = (((size_t)cs * BP + bp) * N4 + n4) * 4 + j;
        a1 += __ldg(pl1 + f);
        a2 += __ldg(pl2 + f);
    }

    const size_t o = (size_t)pair * 3;
    out[o + 0] = a1;
    out[o + 1] = a2;
    out[o + 2] = a1;
}

extern "C" void kernel_launch(void* const* d_in, const int* in_sizes, int n_in,
                              void* d_out, int out_size) {
    const float4* x = (const float4*)d_in[0];
    const float4* y = (const float4*)d_in[1];
    float* out = (float*)d_out;

    sim_partial_kernel<<<BLOCKS1, 256>>>(x, y);
    sim_combine_kernel<<<PAIRS / 256, 256>>>(out);
}

// round 5
// speedup vs baseline: 1.0947x; 1.0947x over previous
#include <cuda_runtime.h>

// SimilarityMeasureModel on GB300 (sm_103a) — FINAL (R2 geometry).
// Inputs: x, y [B=32, P=3, C=512, N=1024] f32 (N contiguous).
// Per (b,p,n): l1 = sum_c |x-y|, l2 = sum_c (x-y)^2 ; out = [l1,l2,l1] interleaved.
//
// Verified at the HBM streaming ceiling: 403.9 MB compulsory traffic at
// ~6.55 TB/s effective (ncu HBM rate == compulsory-bytes rate; zero waste).
// Three alternative geometries (R1 scalar, R3 2x-grid, R4 contiguous-stream
// two-pass) all measured equal-or-slower; this is the floor.

static constexpr int B = 32;
static constexpr int P = 3;
static constexpr int C = 512;
static constexpr int N = 1024;
static constexpr int N4 = N / 4;          // float4 units per row: 256
static constexpr int SEGS = 4;            // C split
static constexpr int CSEG = C / SEGS;     // 128
static constexpr int NV_PER_BLK = 64;     // float4 groups per block -> 256 n values
static constexpr int BLOCKS = (B * P * N) / (NV_PER_BLK * 4);  // 384

__global__ void __launch_bounds__(256, 4)
sim_measure_kernel(const float4* __restrict__ x,
                   const float4* __restrict__ y,
                   float* __restrict__ out) {
    // Block -> (bp, n-quarter)
    const int bid   = blockIdx.x;
    const int bp    = bid >> 2;                 // 0..95  (b*P + p)
    const int nq    = bid & 3;                  // which 256-n chunk
    const int n4off = nq * NV_PER_BLK;          // float4 offset within row

    const int tid = threadIdx.x;
    const int s   = tid >> 6;                   // C-segment 0..3 (2 warps each)
    const int n4  = tid & 63;                   // float4 index within chunk

    const int n4g = n4off + n4;
    size_t idx = ((size_t)bp * C + (size_t)s * CSEG) * N4 + n4g;

    float4 l1 = make_float4(0.f, 0.f, 0.f, 0.f);
    float4 l2 = make_float4(0.f, 0.f, 0.f, 0.f);

    #pragma unroll 4
    for (int c = 0; c < CSEG; ++c) {
        float4 a = __ldg(x + idx);
        float4 b = __ldg(y + idx);
        idx += N4;
        float d0 = a.x - b.x, d1 = a.y - b.y, d2 = a.z - b.z, d3 = a.w - b.w;
        l1.x += fabsf(d0); l1.y += fabsf(d1); l1.z += fabsf(d2); l1.w += fabsf(d3);
        l2.x = fmaf(d0, d0, l2.x); l2.y = fmaf(d1, d1, l2.y);
        l2.z = fmaf(d2, d2, l2.z); l2.w = fmaf(d3, d3, l2.w);
    }

    // Combine the 4 C-segments through shared memory.
    __shared__ float4 sL1[SEGS][NV_PER_BLK];
    __shared__ float4 sL2[SEGS][NV_PER_BLK];
    sL1[s][n4] = l1;
    sL2[s][n4] = l2;
    __syncthreads();

    // 256 threads -> 256 n values of this block; thread t handles n_local = t.
    const int m4 = tid >> 2;      // which float4 group
    const int j  = tid & 3;       // component

    float a1 = 0.f, a2 = 0.f;
    #pragma unroll
    for (int ss = 0; ss < SEGS; ++ss) {
        const float* p1 = (const float*)&sL1[ss][m4];
        const float* p2 = (const float*)&sL2[ss][m4];
        a1 += p1[j];
        a2 += p2[j];
    }

    // pair index = bp*N + nq*256 + tid ; out layout [l1, l2, l1] per pair
    const size_t pair = (size_t)bp * N + (size_t)nq * 256 + tid;
    const size_t o = pair * 3;
    out[o + 0] = a1;
    out[o + 1] = a2;
    out[o + 2] = a1;
}

extern "C" void kernel_launch(void* const* d_in, const int* in_sizes, int n_in,
                              void* d_out, int out_size) {
    const float4* x = (const float4*)d_in[0];
    const float4* y = (const float4*)d_in[1];
    float* out = (float*)d_out;

    sim_measure_kernel<<<BLOCKS, 256>>>(x, y, out);
}

// round 6
// speedup vs baseline: 1.1061x; 1.0104x over previous
#include <cuda_runtime.h>

// SimilarityMeasureModel on GB300 (sm_103a) — R6: R2 geometry + streaming
// cache hints (__ldcs/__stcs) + unroll 8.
// Inputs: x, y [B=32, P=3, C=512, N=1024] f32 (N contiguous).
// Per (b,p,n): l1 = sum_c |x-y|, l2 = sum_c (x-y)^2 ; out = [l1,l2,l1].
//
// At the measured LTS chip cap (~6300 B/cyc path-independent): 403.9 MB
// compulsory traffic at ~6.6 TB/s. This round tests whether evict-first
// L2 policy on the single-touch stream buys back any LTS slots.

static constexpr int B = 32;
static constexpr int P = 3;
static constexpr int C = 512;
static constexpr int N = 1024;
static constexpr int N4 = N / 4;          // float4 units per row: 256
static constexpr int SEGS = 4;            // C split
static constexpr int CSEG = C / SEGS;     // 128
static constexpr int NV_PER_BLK = 64;     // float4 groups per block -> 256 n values
static constexpr int BLOCKS = (B * P * N) / (NV_PER_BLK * 4);  // 384

__global__ void __launch_bounds__(256, 4)
sim_measure_kernel(const float4* __restrict__ x,
                   const float4* __restrict__ y,
                   float* __restrict__ out) {
    // Block -> (bp, n-quarter)
    const int bid   = blockIdx.x;
    const int bp    = bid >> 2;                 // 0..95  (b*P + p)
    const int nq    = bid & 3;                  // which 256-n chunk
    const int n4off = nq * NV_PER_BLK;          // float4 offset within row

    const int tid = threadIdx.x;
    const int s   = tid >> 6;                   // C-segment 0..3 (2 warps each)
    const int n4  = tid & 63;                   // float4 index within chunk

    const int n4g = n4off + n4;
    size_t idx = ((size_t)bp * C + (size_t)s * CSEG) * N4 + n4g;

    float4 l1 = make_float4(0.f, 0.f, 0.f, 0.f);
    float4 l2 = make_float4(0.f, 0.f, 0.f, 0.f);

    #pragma unroll 8
    for (int c = 0; c < CSEG; ++c) {
        float4 a = __ldcs(x + idx);   // streaming: evict-first in L2
        float4 b = __ldcs(y + idx);
        idx += N4;
        float d0 = a.x - b.x, d1 = a.y - b.y, d2 = a.z - b.z, d3 = a.w - b.w;
        l1.x += fabsf(d0); l1.y += fabsf(d1); l1.z += fabsf(d2); l1.w += fabsf(d3);
        l2.x = fmaf(d0, d0, l2.x); l2.y = fmaf(d1, d1, l2.y);
        l2.z = fmaf(d2, d2, l2.z); l2.w = fmaf(d3, d3, l2.w);
    }

    // Combine the 4 C-segments through shared memory.
    __shared__ float4 sL1[SEGS][NV_PER_BLK];
    __shared__ float4 sL2[SEGS][NV_PER_BLK];
    sL1[s][n4] = l1;
    sL2[s][n4] = l2;
    __syncthreads();

    // 256 threads -> 256 n values of this block; thread t handles n_local = t.
    const int m4 = tid >> 2;      // which float4 group
    const int j  = tid & 3;       // component

    float a1 = 0.f, a2 = 0.f;
    #pragma unroll
    for (int ss = 0; ss < SEGS; ++ss) {
        const float* p1 = (const float*)&sL1[ss][m4];
        const float* p2 = (const float*)&sL2[ss][m4];
        a1 += p1[j];
        a2 += p2[j];
    }

    // pair index = bp*N + nq*256 + tid ; out layout [l1, l2, l1] per pair
    const size_t pair = (size_t)bp * N + (size_t)nq * 256 + tid;
    const size_t o = pair * 3;
    __stcs(out + o + 0, a1);
    __stcs(out + o + 1, a2);
    __stcs(out + o + 2, a1);
}

extern "C" void kernel_launch(void* const* d_in, const int* in_sizes, int n_in,
                              void* d_out, int out_size) {
    const float4* x = (const float4*)d_in[0];
    const float4* y = (const float4*)d_in[1];
    float* out = (float*)d_out;

    sim_measure_kernel<<<BLOCKS, 256>>>(x, y, out);
}

// round 7
// speedup vs baseline: 1.1090x; 1.0026x over previous
#include <cuda_runtime.h>

// SimilarityMeasureModel on GB300 (sm_103a) — FINAL.
// Inputs: x, y [B=32, P=3, C=512, N=1024] f32 (N contiguous).
// Per (b,p,n): l1 = sum_c |x-y|, l2 = sum_c (x-y)^2 ; out = [l1,l2,l1] interleaved.
//
// Session conclusion: kernel runs at the B300 LTS chip-throughput cap
// (~6300 B/cyc, path-independent per B300_MICROARCH.md): 403.9 MB compulsory
// traffic @ 6.67 TB/s = 61.5us e2e (>=98% of HW ceiling). Falsified levers:
// occupancy/backfill (R3), DRAM row-locality via contiguous per-block streams
// (R4); confirmed micro-wins: LDG.128 + 4-way C-split (R2), __ldcs/__stcs +
// unroll 8 (R6).

static constexpr int B = 32;
static constexpr int P = 3;
static constexpr int C = 512;
static constexpr int N = 1024;
static constexpr int N4 = N / 4;          // float4 units per row: 256
static constexpr int SEGS = 4;            // C split
static constexpr int CSEG = C / SEGS;     // 128
static constexpr int NV_PER_BLK = 64;     // float4 groups per block -> 256 n values
static constexpr int BLOCKS = (B * P * N) / (NV_PER_BLK * 4);  // 384

__global__ void __launch_bounds__(256, 4)
sim_measure_kernel(const float4* __restrict__ x,
                   const float4* __restrict__ y,
                   float* __restrict__ out) {
    // Block -> (bp, n-quarter)
    const int bid   = blockIdx.x;
    const int bp    = bid >> 2;                 // 0..95  (b*P + p)
    const int nq    = bid & 3;                  // which 256-n chunk
    const int n4off = nq * NV_PER_BLK;          // float4 offset within row

    const int tid = threadIdx.x;
    const int s   = tid >> 6;                   // C-segment 0..3 (2 warps each)
    const int n4  = tid & 63;                   // float4 index within chunk

    const int n4g = n4off + n4;
    size_t idx = ((size_t)bp * C + (size_t)s * CSEG) * N4 + n4g;

    float4 l1 = make_float4(0.f, 0.f, 0.f, 0.f);
    float4 l2 = make_float4(0.f, 0.f, 0.f, 0.f);

    #pragma unroll 8
    for (int c = 0; c < CSEG; ++c) {
        float4 a = __ldcs(x + idx);   // streaming: evict-first in L2
        float4 b = __ldcs(y + idx);
        idx += N4;
        float d0 = a.x - b.x, d1 = a.y - b.y, d2 = a.z - b.z, d3 = a.w - b.w;
        l1.x += fabsf(d0); l1.y += fabsf(d1); l1.z += fabsf(d2); l1.w += fabsf(d3);
        l2.x = fmaf(d0, d0, l2.x); l2.y = fmaf(d1, d1, l2.y);
        l2.z = fmaf(d2, d2, l2.z); l2.w = fmaf(d3, d3, l2.w);
    }

    // Combine the 4 C-segments through shared memory.
    __shared__ float4 sL1[SEGS][NV_PER_BLK];
    __shared__ float4 sL2[SEGS][NV_PER_BLK];
    sL1[s][n4] = l1;
    sL2[s][n4] = l2;
    __syncthreads();

    // 256 threads -> 256 n values of this block; thread t handles n_local = t.
    const int m4 = tid >> 2;      // which float4 group
    const int j  = tid & 3;       // component

    float a1 = 0.f, a2 = 0.f;
    #pragma unroll
    for (int ss = 0; ss < SEGS; ++ss) {
        const float* p1 = (const float*)&sL1[ss][m4];
        const float* p2 = (const float*)&sL2[ss][m4];
        a1 += p1[j];
        a2 += p2[j];
    }

    // pair index = bp*N + nq*256 + tid ; out layout [l1, l2, l1] per pair
    const size_t pair = (size_t)bp * N + (size_t)nq * 256 + tid;
    const size_t o = pair * 3;
    __stcs(out + o + 0, a1);
    __stcs(out + o + 1, a2);
    __stcs(out + o + 2, a1);
}

extern "C" void kernel_launch(void* const* d_in, const int* in_sizes, int n_in,
                              void* d_out, int out_size) {
    const float4* x = (const float4*)d_in[0];
    const float4* y = (const float4*)d_in[1];
    float* out = (float*)d_out;

    sim_measure_kernel<<<BLOCKS, 256>>>(x, y, out);
}